// round 15
// baseline (speedup 1.0000x reference)
#include <cuda_runtime.h>
#include <cuda_bf16.h>
#include <math.h>

// Problem constants
#define BDIM 64
#define TSTEPS 512
#define IDIM 512
#define HDIM 1024

#define NCTAS 128
#define NTHREADS 1024

typedef unsigned long long ull;

// ---------- packed f32x2 helpers ----------
__device__ __forceinline__ ull ffma2(ull a, ull b, ull c) {
    ull d;
    asm("fma.rn.f32x2 %0, %1, %2, %3;" : "=l"(d) : "l"(a), "l"(b), "l"(c));
    return d;
}
__device__ __forceinline__ float lo_f(ull v) {
    return __uint_as_float((unsigned)(v & 0xffffffffull));
}
__device__ __forceinline__ float hi_f(ull v) {
    return __uint_as_float((unsigned)(v >> 32));
}
__device__ __forceinline__ ull dup_f(float x) {
    unsigned u = __float_as_uint(x);
    return ((ull)u << 32) | u;
}
__device__ __forceinline__ unsigned ld_acq(const unsigned* p) {
    unsigned v;
    asm volatile("ld.acquire.gpu.global.u32 %0, [%1];" : "=r"(v) : "l"(p) : "memory");
    return v;
}
__device__ __forceinline__ void red_rel_add1(unsigned* p) {
    asm volatile("red.release.gpu.global.add.u32 [%0], 1;" :: "l"(p) : "memory");
}

// One flag per batch-group, each in its own 128B sector
__device__ unsigned g_flag[4 * 32];
#define FLAG_IDX(gb) ((gb) * 32)

// Contiguous fp32 ping-pong h-exchange buffer
__device__ __align__(16) float g_hx[2][BDIM][HDIM];

// init: h0 -> g_hx[0]; reset flags
__global__ void init_h0(const float* __restrict__ h0) {
    if (blockIdx.x == 0 && threadIdx.x < 4) g_flag[threadIdx.x * 32] = 0u;
    int idx = blockIdx.x * 256 + threadIdx.x;       // 16384 float4 slots
    float4 v = *(const float4*)(h0 + (size_t)idx * 4);
    int b = idx >> 8, g = idx & 255;
    *(float4*)(&g_hx[0][b][g * 4]) = v;
}

// ============================================================
// Kernel 1: xp = embeddings @ Wx^T + bx  -> written into hidden
// (proven R12 gemm: 256 threads, 8x8/thread, FFMA2)
// ============================================================
__global__ __launch_bounds__(256) void gemm_xproj(
    const float* __restrict__ A,
    const float* __restrict__ Bw,
    const float* __restrict__ bx,
    float* __restrict__ C)
{
    const int K = IDIM;
    const int N = HDIM;
    __shared__ ull   As_d[16][130];   // duplicated-pack rows: (a,a)
    __shared__ float Bs[16][132];

    const int bm = blockIdx.y * 128;
    const int bn = blockIdx.x * 128;
    const int tid = threadIdx.x;
    const int tx = tid & 15;          // 8 cols
    const int ty = tid >> 4;          // 8 rows

    ull acc[8][4];
    #pragma unroll
    for (int i = 0; i < 8; i++)
        #pragma unroll
        for (int j = 0; j < 4; j++) acc[i][j] = 0ull;

    for (int kt = 0; kt < K; kt += 16) {
        #pragma unroll
        for (int i = 0; i < 2; i++) {
            int f = tid + 256 * i;
            int row = f >> 2, quad = f & 3;
            float4 v = *(const float4*)(A + (size_t)(bm + row) * K + kt + quad * 4);
            As_d[quad * 4 + 0][row] = dup_f(v.x);
            As_d[quad * 4 + 1][row] = dup_f(v.y);
            As_d[quad * 4 + 2][row] = dup_f(v.z);
            As_d[quad * 4 + 3][row] = dup_f(v.w);
        }
        #pragma unroll
        for (int i = 0; i < 2; i++) {
            int f = tid + 256 * i;
            int col = f >> 2, quad = f & 3;
            float4 v = *(const float4*)(Bw + (size_t)(bn + col) * K + kt + quad * 4);
            Bs[quad * 4 + 0][col] = v.x;
            Bs[quad * 4 + 1][col] = v.y;
            Bs[quad * 4 + 2][col] = v.z;
            Bs[quad * 4 + 3][col] = v.w;
        }
        __syncthreads();

        #pragma unroll
        for (int k = 0; k < 16; k++) {
            ulonglong2 a01 = *(const ulonglong2*)&As_d[k][ty * 8 + 0];
            ulonglong2 a23 = *(const ulonglong2*)&As_d[k][ty * 8 + 2];
            ulonglong2 a45 = *(const ulonglong2*)&As_d[k][ty * 8 + 4];
            ulonglong2 a67 = *(const ulonglong2*)&As_d[k][ty * 8 + 6];
            ulonglong2 b03 = *(const ulonglong2*)&Bs[k][tx * 8 + 0];
            ulonglong2 b47 = *(const ulonglong2*)&Bs[k][tx * 8 + 4];
            ull ad[8] = {a01.x, a01.y, a23.x, a23.y, a45.x, a45.y, a67.x, a67.y};
            ull bp[4] = {b03.x, b03.y, b47.x, b47.y};
            #pragma unroll
            for (int i = 0; i < 8; i++)
                #pragma unroll
                for (int j = 0; j < 4; j++)
                    acc[i][j] = ffma2(ad[i], bp[j], acc[i][j]);
        }
        __syncthreads();
    }

    float4 bx0 = *(const float4*)(bx + bn + tx * 8);
    float4 bx1 = *(const float4*)(bx + bn + tx * 8 + 4);
    #pragma unroll
    for (int i = 0; i < 8; i++) {
        float4 o0, o1;
        o0.x = lo_f(acc[i][0]) + bx0.x;
        o0.y = hi_f(acc[i][0]) + bx0.y;
        o0.z = lo_f(acc[i][1]) + bx0.z;
        o0.w = hi_f(acc[i][1]) + bx0.w;
        o1.x = lo_f(acc[i][2]) + bx1.x;
        o1.y = hi_f(acc[i][2]) + bx1.y;
        o1.z = lo_f(acc[i][3]) + bx1.z;
        o1.w = hi_f(acc[i][3]) + bx1.w;
        float* cp = C + (size_t)(bm + ty * 8 + i) * N + bn + tx * 8;
        *(float4*)(cp)     = o0;
        *(float4*)(cp + 4) = o1;
    }
}

// ============================================================
// Recurrent scan, warp-autonomous pipeline.
// 128 CTAs x 1024 threads. CTA = (gb: 16 batches) x (cg: 32 H cols).
// Warp w owns k-cols [32w, 32w+32) EXCLUSIVELY: it polls the group
// flag itself (lane 0 + syncwarp), stages its own 2KB h-slice into a
// private smem region, and computes with NO full barrier. Only the
// cross-warp reduce needs one __syncthreads; publish is gated by a
// 512-thread named barrier, so non-reducer warps run ahead into the
// next step's poll/stage.
// Safety: red_s rewrite for step t+1 happens only after the flag
// reaches 32(t+1), which requires own-CTA publish, which follows the
// reducers' bar512 — so partials are never overwritten early.
// ============================================================
#define HW_FLOATS  (32 * 16 * 32)          // [warp][bi][32] private slices
#define RED_FLOATS (16 * 32 * 33)
#define SMEM_BYTES ((HW_FLOATS + RED_FLOATS) * 4)

__global__ __launch_bounds__(NTHREADS, 1) void rnn_scan(
    float* __restrict__ hidden,      // [B, T, H] holds xp, overwritten with h
    const float* __restrict__ Wh,    // [H, H]
    const float* __restrict__ bh,    // [H]
    float* __restrict__ lasth)       // [B, H]
{
    extern __shared__ float smem[];
    float* hw_s  = smem;               // [32][16][32] warp-private
    float* red_s = smem + HW_FLOATS;   // [bi][col][warp] pad 33

    const int tid = threadIdx.x;
    const int l = tid & 31;
    const int w = tid >> 5;            // warp 0..31, owns k [32w, 32w+32)
    const int cp = l & 15;             // col-pair index
    const int kh = l >> 4;             // 0/1
    const int kq = 2 * w + kh;         // k window [16kq, 16kq+16)
    const int gb = blockIdx.x & 3;
    const int cg = blockIdx.x >> 2;
    const int b0 = gb * 16;
    const int c0 = cg * 32 + 2 * cp;

    // Persistent packed weights: 2 cols x 8 k-pairs = 16 ull (32 regs)
    ull wp0[8], wp1[8];
    {
        const ulonglong2* s0 = (const ulonglong2*)(Wh + (size_t)c0 * HDIM + kq * 16);
        const ulonglong2* s1 = (const ulonglong2*)(Wh + (size_t)(c0 + 1) * HDIM + kq * 16);
        #pragma unroll
        for (int q = 0; q < 4; q++) {
            ulonglong2 v = s0[q];
            wp0[2 * q + 0] = v.x;
            wp0[2 * q + 1] = v.y;
            ulonglong2 u = s1[q];
            wp1[2 * q + 0] = u.x;
            wp1[2 * q + 1] = u.y;
        }
    }

    const int colsel = 2 * cp + kh;

    // Epilogue mapping (threads 0..511 only)
    const int bi_e = (tid >> 5) & 15;
    const int col_e = tid & 31;
    const int b_e = b0 + bi_e;
    const int h_e = cg * 32 + col_e;
    const float bh_r = bh[h_e];

    // staging jobs: 4 float4 per lane (warp covers 16 bi x 8 float4)
    const int sj_bi[4] = {l >> 3, (l + 32) >> 3, (l + 64) >> 3, (l + 96) >> 3};
    const int sj_c4[4] = {l & 7, l & 7, l & 7, l & 7};

    float* hw_w = hw_s + w * 512;                 // this warp's region
    const float* hk = hw_w + kh * 16;             // this thread's k half

    unsigned* flag = &g_flag[FLAG_IDX(gb)];

    for (int t = 0; t < TSTEPS; t++) {
        // ---- xp prefetch (own slot; independent of h_prev) ----
        size_t oidx = 0;
        float xp_val = 0.0f;
        if (tid < 512) {
            oidx = ((size_t)b_e * TSTEPS + t) * HDIM + h_e;
            xp_val = __ldg(hidden + oidx);
        }

        // ---- warp-autonomous wait ----
        if (t > 0) {
            if (l == 0) {
                const unsigned target = 32u * (unsigned)t;
                while (ld_acq(flag) < target) { }
            }
            __syncwarp();
        }

        // ---- warp-private stage: 2KB = 16 bi x 32 floats of own k-cols ----
        {
            const float* base = &g_hx[t & 1][b0][w * 32];
            #pragma unroll
            for (int j = 0; j < 4; j++) {
                float4 v = __ldcg((const float4*)(base
                            + (size_t)sj_bi[j] * HDIM + sj_c4[j] * 4));
                *(float4*)(hw_w + sj_bi[j] * 32 + sj_c4[j] * 4) = v;
            }
        }
        __syncwarp();

        // ---- 16 batches x (2 cols x 16 k); reduce-and-store per bi ----
        #pragma unroll 4
        for (int bi = 0; bi < 16; bi++) {
            const ulonglong2* hp = (const ulonglong2*)(hk + bi * 32);
            ulonglong2 u0 = hp[0];
            ulonglong2 u1 = hp[1];
            ull a0  = ffma2(u0.x, wp0[0], 0ull);
            ull a1  = ffma2(u0.x, wp1[0], 0ull);
            ull a0b = ffma2(u0.y, wp0[1], 0ull);
            ull a1b = ffma2(u0.y, wp1[1], 0ull);
            a0  = ffma2(u1.x, wp0[2], a0);
            a1  = ffma2(u1.x, wp1[2], a1);
            a0b = ffma2(u1.y, wp0[3], a0b);
            a1b = ffma2(u1.y, wp1[3], a1b);
            ulonglong2 u2 = hp[2];
            ulonglong2 u3 = hp[3];
            a0  = ffma2(u2.x, wp0[4], a0);
            a1  = ffma2(u2.x, wp1[4], a1);
            a0b = ffma2(u2.y, wp0[5], a0b);
            a1b = ffma2(u2.y, wp1[5], a1b);
            a0  = ffma2(u3.x, wp0[6], a0);
            a1  = ffma2(u3.x, wp1[6], a1);
            a0b = ffma2(u3.y, wp0[7], a0b);
            a1b = ffma2(u3.y, wp1[7], a1b);
            float s0 = (lo_f(a0) + hi_f(a0)) + (lo_f(a0b) + hi_f(a0b));
            float s1 = (lo_f(a1) + hi_f(a1)) + (lo_f(a1b) + hi_f(a1b));
            s0 += __shfl_xor_sync(0xffffffffu, s0, 16);
            s1 += __shfl_xor_sync(0xffffffffu, s1, 16);
            red_s[(bi * 32 + colsel) * 33 + w] = (l < 16) ? s0 : s1;
        }
        __syncthreads();   // all warps' partials visible

        // ---- final reduce (dual chain) + epilogue (threads 0..511) ----
        if (tid < 512) {
            const float* rp = red_s + (bi_e * 32 + col_e) * 33;
            float sa = 0.0f, sb = 0.0f;
            #pragma unroll
            for (int ww = 0; ww < 16; ww++) {
                sa += rp[ww];
                sb += rp[ww + 16];
            }
            const float val = tanhf(xp_val + sa + sb + bh_r);
            g_hx[(t + 1) & 1][b_e][h_e] = val;          // exchange write first
            hidden[oidx] = val;                          // output record
            if (t == TSTEPS - 1)
                lasth[(size_t)b_e * HDIM + h_e] = val;

            // reducers-only barrier, then publish
            asm volatile("bar.sync 1, 512;" ::: "memory");
            if (tid == 0) red_rel_add1(flag);
        }
        // warps 16..31 continue into step t+1 immediately (their next
        // red_s write is gated by the flag passing 32(t+1)).
    }
}

// ============================================================
// Launch
// ============================================================
extern "C" void kernel_launch(void* const* d_in, const int* in_sizes, int n_in,
                              void* d_out, int out_size) {
    const float* emb = (const float*)d_in[0];   // [B,T,I]
    const float* h0  = (const float*)d_in[1];   // [B,H]
    const float* Wx  = (const float*)d_in[2];   // [H,I]
    const float* bx  = (const float*)d_in[3];   // [H]
    const float* Wh  = (const float*)d_in[4];   // [H,H]
    const float* bh  = (const float*)d_in[5];   // [H]

    float* hidden = (float*)d_out;                            // [B,T,H]
    float* lasth  = hidden + (size_t)BDIM * TSTEPS * HDIM;    // [B,H]

    cudaFuncSetAttribute(rnn_scan, cudaFuncAttributeMaxDynamicSharedMemorySize,
                         SMEM_BYTES);

    // h0 -> exchange buffer, reset flags
    init_h0<<<64, 256>>>(h0);

    // xp = emb @ Wx^T + bx
    dim3 g1(HDIM / 128, (BDIM * TSTEPS) / 128);
    gemm_xproj<<<g1, 256>>>(emb, Wx, bx, hidden);

    // dataflow-synced persistent scan
    rnn_scan<<<NCTAS, NTHREADS, SMEM_BYTES>>>(hidden, Wh, bh, lasth);
}

// round 16
// speedup vs baseline: 1.0906x; 1.0906x over previous
#include <cuda_runtime.h>
#include <cuda_bf16.h>
#include <math.h>

// Problem constants
#define BDIM 64
#define TSTEPS 512
#define IDIM 512
#define HDIM 1024

#define NCTAS 128
#define NTHREADS 1024

typedef unsigned long long ull;

// ---------- packed f32x2 helpers ----------
__device__ __forceinline__ ull ffma2(ull a, ull b, ull c) {
    ull d;
    asm("fma.rn.f32x2 %0, %1, %2, %3;" : "=l"(d) : "l"(a), "l"(b), "l"(c));
    return d;
}
__device__ __forceinline__ float lo_f(ull v) {
    return __uint_as_float((unsigned)(v & 0xffffffffull));
}
__device__ __forceinline__ float hi_f(ull v) {
    return __uint_as_float((unsigned)(v >> 32));
}
__device__ __forceinline__ ull dup_f(float x) {
    unsigned u = __float_as_uint(x);
    return ((ull)u << 32) | u;
}
__device__ __forceinline__ unsigned ld_rlx(const unsigned* p) {
    unsigned v;
    asm volatile("ld.relaxed.gpu.global.u32 %0, [%1];" : "=r"(v) : "l"(p) : "memory");
    return v;
}
__device__ __forceinline__ unsigned ld_acq(const unsigned* p) {
    unsigned v;
    asm volatile("ld.acquire.gpu.global.u32 %0, [%1];" : "=r"(v) : "l"(p) : "memory");
    return v;
}
__device__ __forceinline__ void red_rel_add1(unsigned* p) {
    asm volatile("red.release.gpu.global.add.u32 [%0], 1;" :: "l"(p) : "memory");
}

// One flag per batch-group, each in its own 128B sector
__device__ unsigned g_flag[4 * 32];
#define FLAG_IDX(gb) ((gb) * 32)

// Contiguous fp32 ping-pong h-exchange buffer
__device__ __align__(16) float g_hx[2][BDIM][HDIM];

// init: h0 -> g_hx[0]; reset flags
__global__ void init_h0(const float* __restrict__ h0) {
    if (blockIdx.x == 0 && threadIdx.x < 4) g_flag[threadIdx.x * 32] = 0u;
    int idx = blockIdx.x * 256 + threadIdx.x;       // 16384 float4 slots
    float4 v = *(const float4*)(h0 + (size_t)idx * 4);
    int b = idx >> 8, g = idx & 255;
    *(float4*)(&g_hx[0][b][g * 4]) = v;
}

// ============================================================
// Kernel 1: xp = embeddings @ Wx^T + bx  -> written into hidden
// (proven R12 gemm: 256 threads, 8x8/thread, FFMA2)
// ============================================================
__global__ __launch_bounds__(256) void gemm_xproj(
    const float* __restrict__ A,
    const float* __restrict__ Bw,
    const float* __restrict__ bx,
    float* __restrict__ C)
{
    const int K = IDIM;
    const int N = HDIM;
    __shared__ ull   As_d[16][130];   // duplicated-pack rows: (a,a)
    __shared__ float Bs[16][132];

    const int bm = blockIdx.y * 128;
    const int bn = blockIdx.x * 128;
    const int tid = threadIdx.x;
    const int tx = tid & 15;          // 8 cols
    const int ty = tid >> 4;          // 8 rows

    ull acc[8][4];
    #pragma unroll
    for (int i = 0; i < 8; i++)
        #pragma unroll
        for (int j = 0; j < 4; j++) acc[i][j] = 0ull;

    for (int kt = 0; kt < K; kt += 16) {
        #pragma unroll
        for (int i = 0; i < 2; i++) {
            int f = tid + 256 * i;
            int row = f >> 2, quad = f & 3;
            float4 v = *(const float4*)(A + (size_t)(bm + row) * K + kt + quad * 4);
            As_d[quad * 4 + 0][row] = dup_f(v.x);
            As_d[quad * 4 + 1][row] = dup_f(v.y);
            As_d[quad * 4 + 2][row] = dup_f(v.z);
            As_d[quad * 4 + 3][row] = dup_f(v.w);
        }
        #pragma unroll
        for (int i = 0; i < 2; i++) {
            int f = tid + 256 * i;
            int col = f >> 2, quad = f & 3;
            float4 v = *(const float4*)(Bw + (size_t)(bn + col) * K + kt + quad * 4);
            Bs[quad * 4 + 0][col] = v.x;
            Bs[quad * 4 + 1][col] = v.y;
            Bs[quad * 4 + 2][col] = v.z;
            Bs[quad * 4 + 3][col] = v.w;
        }
        __syncthreads();

        #pragma unroll
        for (int k = 0; k < 16; k++) {
            ulonglong2 a01 = *(const ulonglong2*)&As_d[k][ty * 8 + 0];
            ulonglong2 a23 = *(const ulonglong2*)&As_d[k][ty * 8 + 2];
            ulonglong2 a45 = *(const ulonglong2*)&As_d[k][ty * 8 + 4];
            ulonglong2 a67 = *(const ulonglong2*)&As_d[k][ty * 8 + 6];
            ulonglong2 b03 = *(const ulonglong2*)&Bs[k][tx * 8 + 0];
            ulonglong2 b47 = *(const ulonglong2*)&Bs[k][tx * 8 + 4];
            ull ad[8] = {a01.x, a01.y, a23.x, a23.y, a45.x, a45.y, a67.x, a67.y};
            ull bp[4] = {b03.x, b03.y, b47.x, b47.y};
            #pragma unroll
            for (int i = 0; i < 8; i++)
                #pragma unroll
                for (int j = 0; j < 4; j++)
                    acc[i][j] = ffma2(ad[i], bp[j], acc[i][j]);
        }
        __syncthreads();
    }

    float4 bx0 = *(const float4*)(bx + bn + tx * 8);
    float4 bx1 = *(const float4*)(bx + bn + tx * 8 + 4);
    #pragma unroll
    for (int i = 0; i < 8; i++) {
        float4 o0, o1;
        o0.x = lo_f(acc[i][0]) + bx0.x;
        o0.y = hi_f(acc[i][0]) + bx0.y;
        o0.z = lo_f(acc[i][1]) + bx0.z;
        o0.w = hi_f(acc[i][1]) + bx0.w;
        o1.x = lo_f(acc[i][2]) + bx1.x;
        o1.y = hi_f(acc[i][2]) + bx1.y;
        o1.z = lo_f(acc[i][3]) + bx1.z;
        o1.w = hi_f(acc[i][3]) + bx1.w;
        float* cp = C + (size_t)(bm + ty * 8 + i) * N + bn + tx * 8;
        *(float4*)(cp)     = o0;
        *(float4*)(cp + 4) = o1;
    }
}

// ============================================================
// Recurrent scan (R12 champion structure + deferred output stores).
// 128 CTAs x 1024 threads. CTA = (gb: 16 batches) x (cg: 32 H cols).
// Thread (w, l): cols {cg*32 + 2*(l&15), +1}; kq = 2w + (l>>4),
// k in [16kq, 16kq+16). Weights 16 ull = 32 regs, persistent.
// Critical path per step: tid0 relaxed-poll -> bar -> dense 64KB
// stage -> compute -> partials -> reduce+tanh -> g_hx write -> bar ->
// publish.  hidden/lasth output STGs happen AFTER publish (not
// consumer-visible; off the serial chain).
// ============================================================
#define HS_FLOATS  (16 * 1024)
#define RED_FLOATS (16 * 32 * 33)
#define SMEM_BYTES ((HS_FLOATS + RED_FLOATS) * 4)

__global__ __launch_bounds__(NTHREADS, 1) void rnn_scan(
    float* __restrict__ hidden,      // [B, T, H] holds xp, overwritten with h
    const float* __restrict__ Wh,    // [H, H]
    const float* __restrict__ bh,    // [H]
    float* __restrict__ lasth)       // [B, H]
{
    extern __shared__ float smem[];
    float* h_s   = smem;               // [16][1024]
    float* red_s = smem + HS_FLOATS;   // [bi][col][warp] pad 33

    const int tid = threadIdx.x;
    const int l = tid & 31;
    const int w = tid >> 5;            // warp 0..31
    const int cp = l & 15;             // col-pair index
    const int kh = l >> 4;             // 0/1
    const int kq = 2 * w + kh;         // 0..63
    const int gb = blockIdx.x & 3;
    const int cg = blockIdx.x >> 2;
    const int b0 = gb * 16;
    const int c0 = cg * 32 + 2 * cp;

    // Persistent packed weights: 2 cols x 8 k-pairs = 16 ull (32 regs)
    ull wp0[8], wp1[8];
    {
        const ulonglong2* s0 = (const ulonglong2*)(Wh + (size_t)c0 * HDIM + kq * 16);
        const ulonglong2* s1 = (const ulonglong2*)(Wh + (size_t)(c0 + 1) * HDIM + kq * 16);
        #pragma unroll
        for (int q = 0; q < 4; q++) {
            ulonglong2 v = s0[q];
            wp0[2 * q + 0] = v.x;
            wp0[2 * q + 1] = v.y;
            ulonglong2 u = s1[q];
            wp1[2 * q + 0] = u.x;
            wp1[2 * q + 1] = u.y;
        }
    }

    const int colsel = 2 * cp + kh;

    // Epilogue mapping (threads 0..511 only)
    const int bi_e = (tid >> 5) & 15;
    const int col_e = tid & 31;
    const int b_e = b0 + bi_e;
    const int h_e = cg * 32 + col_e;
    const float bh_r = bh[h_e];

    const float* hk = h_s + kq * 16;
    unsigned* flag = &g_flag[FLAG_IDX(gb)];

    for (int t = 0; t < TSTEPS; t++) {
        // ---- xp prefetch (own slot; independent of h_prev) ----
        size_t oidx = 0;
        float xp_val = 0.0f;
        if (tid < 512) {
            oidx = ((size_t)b_e * TSTEPS + t) * HDIM + h_e;
            xp_val = __ldg(hidden + oidx);
        }

        // ---- wait for all 32 col-CTAs of this group (relaxed poll) ----
        if (t > 0 && tid == 0) {
            const unsigned target = 32u * (unsigned)t;
            while (ld_rlx(flag) < target) { }
            (void)ld_acq(flag);   // establish acquire ordering once
        }
        __syncthreads();

        // ---- stage h_prev from dense exchange buffer (64KB stream) ----
        {
            const float* base = &g_hx[t & 1][b0][0];    // 16 contiguous rows
            #pragma unroll
            for (int i = 0; i < 4; i++) {
                int idx = tid + NTHREADS * i;           // 0..4095 float4 slots
                float4 v = __ldcg((const float4*)(base + idx * 4));
                *(float4*)(h_s + idx * 4) = v;
            }
        }
        __syncthreads();

        // ---- 16 batches x (2 cols x 16 k); reduce-and-store per bi ----
        #pragma unroll 4
        for (int bi = 0; bi < 16; bi++) {
            const ulonglong2* hp = (const ulonglong2*)(hk + bi * 1024);
            ulonglong2 u0 = hp[0];
            ulonglong2 u1 = hp[1];
            ull a0  = ffma2(u0.x, wp0[0], 0ull);
            ull a1  = ffma2(u0.x, wp1[0], 0ull);
            ull a0b = ffma2(u0.y, wp0[1], 0ull);
            ull a1b = ffma2(u0.y, wp1[1], 0ull);
            a0  = ffma2(u1.x, wp0[2], a0);
            a1  = ffma2(u1.x, wp1[2], a1);
            a0b = ffma2(u1.y, wp0[3], a0b);
            a1b = ffma2(u1.y, wp1[3], a1b);
            ulonglong2 u2 = hp[2];
            ulonglong2 u3 = hp[3];
            a0  = ffma2(u2.x, wp0[4], a0);
            a1  = ffma2(u2.x, wp1[4], a1);
            a0b = ffma2(u2.y, wp0[5], a0b);
            a1b = ffma2(u2.y, wp1[5], a1b);
            a0  = ffma2(u3.x, wp0[6], a0);
            a1  = ffma2(u3.x, wp1[6], a1);
            a0b = ffma2(u3.y, wp0[7], a0b);
            a1b = ffma2(u3.y, wp1[7], a1b);
            float s0 = (lo_f(a0) + hi_f(a0)) + (lo_f(a0b) + hi_f(a0b));
            float s1 = (lo_f(a1) + hi_f(a1)) + (lo_f(a1b) + hi_f(a1b));
            s0 += __shfl_xor_sync(0xffffffffu, s0, 16);
            s1 += __shfl_xor_sync(0xffffffffu, s1, 16);
            red_s[(bi * 32 + colsel) * 33 + w] = (l < 16) ? s0 : s1;
        }
        __syncthreads();

        // ---- final reduce (dual chain) + exchange write ----
        float val = 0.0f;
        if (tid < 512) {
            const float* rp = red_s + (bi_e * 32 + col_e) * 33;
            float sa = 0.0f, sb = 0.0f;
            #pragma unroll
            for (int ww = 0; ww < 16; ww++) {
                sa += rp[ww];
                sb += rp[ww + 16];
            }
            val = tanhf(xp_val + sa + sb + bh_r);
            g_hx[(t + 1) & 1][b_e][h_e] = val;          // consumer-visible write
        }

        // ---- publish (only g_hx must be ordered before it) ----
        __syncthreads();
        if (tid == 0) red_rel_add1(flag);

        // ---- deferred output stores (off the critical path) ----
        if (tid < 512) {
            hidden[oidx] = val;
            if (t == TSTEPS - 1)
                lasth[(size_t)b_e * HDIM + h_e] = val;
        }
    }
}

// ============================================================
// Launch
// ============================================================
extern "C" void kernel_launch(void* const* d_in, const int* in_sizes, int n_in,
                              void* d_out, int out_size) {
    const float* emb = (const float*)d_in[0];   // [B,T,I]
    const float* h0  = (const float*)d_in[1];   // [B,H]
    const float* Wx  = (const float*)d_in[2];   // [H,I]
    const float* bx  = (const float*)d_in[3];   // [H]
    const float* Wh  = (const float*)d_in[4];   // [H,H]
    const float* bh  = (const float*)d_in[5];   // [H]

    float* hidden = (float*)d_out;                            // [B,T,H]
    float* lasth  = hidden + (size_t)BDIM * TSTEPS * HDIM;    // [B,H]

    cudaFuncSetAttribute(rnn_scan, cudaFuncAttributeMaxDynamicSharedMemorySize,
                         SMEM_BYTES);

    // h0 -> exchange buffer, reset flags
    init_h0<<<64, 256>>>(h0);

    // xp = emb @ Wx^T + bx
    dim3 g1(HDIM / 128, (BDIM * TSTEPS) / 128);
    gemm_xproj<<<g1, 256>>>(emb, Wx, bx, hidden);

    // dataflow-synced persistent scan
    rnn_scan<<<NCTAS, NTHREADS, SMEM_BYTES>>>(hidden, Wh, bh, lasth);
}

// round 17
// speedup vs baseline: 1.0928x; 1.0020x over previous
#include <cuda_runtime.h>
#include <cuda_bf16.h>
#include <math.h>

// Problem constants
#define BDIM 64
#define TSTEPS 512
#define IDIM 512
#define HDIM 1024

#define NCTAS 128
#define NTHREADS 1024

typedef unsigned long long ull;

// ---------- packed f32x2 helpers ----------
__device__ __forceinline__ ull ffma2(ull a, ull b, ull c) {
    ull d;
    asm("fma.rn.f32x2 %0, %1, %2, %3;" : "=l"(d) : "l"(a), "l"(b), "l"(c));
    return d;
}
__device__ __forceinline__ float lo_f(ull v) {
    return __uint_as_float((unsigned)(v & 0xffffffffull));
}
__device__ __forceinline__ float hi_f(ull v) {
    return __uint_as_float((unsigned)(v >> 32));
}
__device__ __forceinline__ ull dup_f(float x) {
    unsigned u = __float_as_uint(x);
    return ((ull)u << 32) | u;
}
__device__ __forceinline__ unsigned ld_rlx(const unsigned* p) {
    unsigned v;
    asm volatile("ld.relaxed.gpu.global.u32 %0, [%1];" : "=r"(v) : "l"(p) : "memory");
    return v;
}
__device__ __forceinline__ unsigned ld_acq(const unsigned* p) {
    unsigned v;
    asm volatile("ld.acquire.gpu.global.u32 %0, [%1];" : "=r"(v) : "l"(p) : "memory");
    return v;
}
__device__ __forceinline__ void red_rel_add1(unsigned* p) {
    asm volatile("red.release.gpu.global.add.u32 [%0], 1;" :: "l"(p) : "memory");
}

// One flag per batch-group, each in its own 128B sector
__device__ unsigned g_flag[4 * 32];
#define FLAG_IDX(gb) ((gb) * 32)

// Contiguous fp32 ping-pong h-exchange buffer
__device__ __align__(16) float g_hx[2][BDIM][HDIM];

// init: h0 -> g_hx[0]; reset flags
__global__ void init_h0(const float* __restrict__ h0) {
    if (blockIdx.x == 0 && threadIdx.x < 4) g_flag[threadIdx.x * 32] = 0u;
    int idx = blockIdx.x * 256 + threadIdx.x;       // 16384 float4 slots
    float4 v = *(const float4*)(h0 + (size_t)idx * 4);
    int b = idx >> 8, g = idx & 255;
    *(float4*)(&g_hx[0][b][g * 4]) = v;
}

// ============================================================
// Kernel 1: xp = embeddings @ Wx^T + bx  -> written into hidden
// (proven R12 gemm: 256 threads, 8x8/thread, FFMA2)
// ============================================================
__global__ __launch_bounds__(256) void gemm_xproj(
    const float* __restrict__ A,
    const float* __restrict__ Bw,
    const float* __restrict__ bx,
    float* __restrict__ C)
{
    const int K = IDIM;
    const int N = HDIM;
    __shared__ ull   As_d[16][130];   // duplicated-pack rows: (a,a)
    __shared__ float Bs[16][132];

    const int bm = blockIdx.y * 128;
    const int bn = blockIdx.x * 128;
    const int tid = threadIdx.x;
    const int tx = tid & 15;          // 8 cols
    const int ty = tid >> 4;          // 8 rows

    ull acc[8][4];
    #pragma unroll
    for (int i = 0; i < 8; i++)
        #pragma unroll
        for (int j = 0; j < 4; j++) acc[i][j] = 0ull;

    for (int kt = 0; kt < K; kt += 16) {
        #pragma unroll
        for (int i = 0; i < 2; i++) {
            int f = tid + 256 * i;
            int row = f >> 2, quad = f & 3;
            float4 v = *(const float4*)(A + (size_t)(bm + row) * K + kt + quad * 4);
            As_d[quad * 4 + 0][row] = dup_f(v.x);
            As_d[quad * 4 + 1][row] = dup_f(v.y);
            As_d[quad * 4 + 2][row] = dup_f(v.z);
            As_d[quad * 4 + 3][row] = dup_f(v.w);
        }
        #pragma unroll
        for (int i = 0; i < 2; i++) {
            int f = tid + 256 * i;
            int col = f >> 2, quad = f & 3;
            float4 v = *(const float4*)(Bw + (size_t)(bn + col) * K + kt + quad * 4);
            Bs[quad * 4 + 0][col] = v.x;
            Bs[quad * 4 + 1][col] = v.y;
            Bs[quad * 4 + 2][col] = v.z;
            Bs[quad * 4 + 3][col] = v.w;
        }
        __syncthreads();

        #pragma unroll
        for (int k = 0; k < 16; k++) {
            ulonglong2 a01 = *(const ulonglong2*)&As_d[k][ty * 8 + 0];
            ulonglong2 a23 = *(const ulonglong2*)&As_d[k][ty * 8 + 2];
            ulonglong2 a45 = *(const ulonglong2*)&As_d[k][ty * 8 + 4];
            ulonglong2 a67 = *(const ulonglong2*)&As_d[k][ty * 8 + 6];
            ulonglong2 b03 = *(const ulonglong2*)&Bs[k][tx * 8 + 0];
            ulonglong2 b47 = *(const ulonglong2*)&Bs[k][tx * 8 + 4];
            ull ad[8] = {a01.x, a01.y, a23.x, a23.y, a45.x, a45.y, a67.x, a67.y};
            ull bp[4] = {b03.x, b03.y, b47.x, b47.y};
            #pragma unroll
            for (int i = 0; i < 8; i++)
                #pragma unroll
                for (int j = 0; j < 4; j++)
                    acc[i][j] = ffma2(ad[i], bp[j], acc[i][j]);
        }
        __syncthreads();
    }

    float4 bx0 = *(const float4*)(bx + bn + tx * 8);
    float4 bx1 = *(const float4*)(bx + bn + tx * 8 + 4);
    #pragma unroll
    for (int i = 0; i < 8; i++) {
        float4 o0, o1;
        o0.x = lo_f(acc[i][0]) + bx0.x;
        o0.y = hi_f(acc[i][0]) + bx0.y;
        o0.z = lo_f(acc[i][1]) + bx0.z;
        o0.w = hi_f(acc[i][1]) + bx0.w;
        o1.x = lo_f(acc[i][2]) + bx1.x;
        o1.y = hi_f(acc[i][2]) + bx1.y;
        o1.z = lo_f(acc[i][3]) + bx1.z;
        o1.w = hi_f(acc[i][3]) + bx1.w;
        float* cp = C + (size_t)(bm + ty * 8 + i) * N + bn + tx * 8;
        *(float4*)(cp)     = o0;
        *(float4*)(cp + 4) = o1;
    }
}

// ============================================================
// Recurrent scan: central poll (R16) + warp-private staging (R15's
// good half). Per step: tid0 relaxed-poll -> full bar -> each warp
// stages ITS OWN 2KB slice (16 bi x 32 own k-cols) -> __syncwarp ->
// compute -> partials -> full bar -> reduce+tanh -> g_hx -> bar ->
// publish -> deferred hidden/lasth stores.  3 full bars (was 4), and
// each warp's compute waits only on its own L2 loads.
// ============================================================
#define HW_FLOATS  (32 * 16 * 32)          // [warp][bi][32] private slices
#define RED_FLOATS (16 * 32 * 33)
#define SMEM_BYTES ((HW_FLOATS + RED_FLOATS) * 4)

__global__ __launch_bounds__(NTHREADS, 1) void rnn_scan(
    float* __restrict__ hidden,      // [B, T, H] holds xp, overwritten with h
    const float* __restrict__ Wh,    // [H, H]
    const float* __restrict__ bh,    // [H]
    float* __restrict__ lasth)       // [B, H]
{
    extern __shared__ float smem[];
    float* hw_s  = smem;               // [32][16][32] warp-private
    float* red_s = smem + HW_FLOATS;   // [bi][col][warp] pad 33

    const int tid = threadIdx.x;
    const int l = tid & 31;
    const int w = tid >> 5;            // warp 0..31, owns k [32w, 32w+32)
    const int cp = l & 15;             // col-pair index
    const int kh = l >> 4;             // 0/1
    const int kq = 2 * w + kh;         // k window [16kq, 16kq+16)
    const int gb = blockIdx.x & 3;
    const int cg = blockIdx.x >> 2;
    const int b0 = gb * 16;
    const int c0 = cg * 32 + 2 * cp;

    // Persistent packed weights: 2 cols x 8 k-pairs = 16 ull (32 regs)
    ull wp0[8], wp1[8];
    {
        const ulonglong2* s0 = (const ulonglong2*)(Wh + (size_t)c0 * HDIM + kq * 16);
        const ulonglong2* s1 = (const ulonglong2*)(Wh + (size_t)(c0 + 1) * HDIM + kq * 16);
        #pragma unroll
        for (int q = 0; q < 4; q++) {
            ulonglong2 v = s0[q];
            wp0[2 * q + 0] = v.x;
            wp0[2 * q + 1] = v.y;
            ulonglong2 u = s1[q];
            wp1[2 * q + 0] = u.x;
            wp1[2 * q + 1] = u.y;
        }
    }

    const int colsel = 2 * cp + kh;

    // Epilogue mapping (threads 0..511 only)
    const int bi_e = (tid >> 5) & 15;
    const int col_e = tid & 31;
    const int b_e = b0 + bi_e;
    const int h_e = cg * 32 + col_e;
    const float bh_r = bh[h_e];

    // staging jobs: 4 float4 per lane (warp covers 16 bi x 8 float4)
    const int sj0 = l >> 3;            // bi for job j: sj0 + 4j
    const int sc4 = l & 7;             // float4 index within 32 cols

    float* hw_w = hw_s + w * 512;      // this warp's region
    const float* hk = hw_w + kh * 16;  // this thread's k half

    unsigned* flag = &g_flag[FLAG_IDX(gb)];

    for (int t = 0; t < TSTEPS; t++) {
        // ---- xp prefetch (own slot; independent of h_prev) ----
        size_t oidx = 0;
        float xp_val = 0.0f;
        if (tid < 512) {
            oidx = ((size_t)b_e * TSTEPS + t) * HDIM + h_e;
            xp_val = __ldg(hidden + oidx);
        }

        // ---- central wait: tid0 relaxed-poll, then full bar ----
        if (t > 0 && tid == 0) {
            const unsigned target = 32u * (unsigned)t;
            while (ld_rlx(flag) < target) { }
            (void)ld_acq(flag);
        }
        __syncthreads();

        // ---- warp-private stage: 16 bi x 32 own k-cols (2KB) ----
        {
            const float* base = &g_hx[t & 1][b0][w * 32];
            #pragma unroll
            for (int j = 0; j < 4; j++) {
                const int bi = sj0 + 4 * j;
                float4 v = __ldcg((const float4*)(base
                            + (size_t)bi * HDIM + sc4 * 4));
                *(float4*)(hw_w + bi * 32 + sc4 * 4) = v;
            }
        }
        __syncwarp();   // own warp's slice ready; no full-CTA bar

        // ---- 16 batches x (2 cols x 16 k); reduce-and-store per bi ----
        #pragma unroll 4
        for (int bi = 0; bi < 16; bi++) {
            const ulonglong2* hp = (const ulonglong2*)(hk + bi * 32);
            ulonglong2 u0 = hp[0];
            ulonglong2 u1 = hp[1];
            ull a0  = ffma2(u0.x, wp0[0], 0ull);
            ull a1  = ffma2(u0.x, wp1[0], 0ull);
            ull a0b = ffma2(u0.y, wp0[1], 0ull);
            ull a1b = ffma2(u0.y, wp1[1], 0ull);
            a0  = ffma2(u1.x, wp0[2], a0);
            a1  = ffma2(u1.x, wp1[2], a1);
            a0b = ffma2(u1.y, wp0[3], a0b);
            a1b = ffma2(u1.y, wp1[3], a1b);
            ulonglong2 u2 = hp[2];
            ulonglong2 u3 = hp[3];
            a0  = ffma2(u2.x, wp0[4], a0);
            a1  = ffma2(u2.x, wp1[4], a1);
            a0b = ffma2(u2.y, wp0[5], a0b);
            a1b = ffma2(u2.y, wp1[5], a1b);
            a0  = ffma2(u3.x, wp0[6], a0);
            a1  = ffma2(u3.x, wp1[6], a1);
            a0b = ffma2(u3.y, wp0[7], a0b);
            a1b = ffma2(u3.y, wp1[7], a1b);
            float s0 = (lo_f(a0) + hi_f(a0)) + (lo_f(a0b) + hi_f(a0b));
            float s1 = (lo_f(a1) + hi_f(a1)) + (lo_f(a1b) + hi_f(a1b));
            s0 += __shfl_xor_sync(0xffffffffu, s0, 16);
            s1 += __shfl_xor_sync(0xffffffffu, s1, 16);
            red_s[(bi * 32 + colsel) * 33 + w] = (l < 16) ? s0 : s1;
        }
        __syncthreads();   // all warps' partials visible

        // ---- final reduce (dual chain) + exchange write ----
        float val = 0.0f;
        if (tid < 512) {
            const float* rp = red_s + (bi_e * 32 + col_e) * 33;
            float sa = 0.0f, sb = 0.0f;
            #pragma unroll
            for (int ww = 0; ww < 16; ww++) {
                sa += rp[ww];
                sb += rp[ww + 16];
            }
            val = tanhf(xp_val + sa + sb + bh_r);
            g_hx[(t + 1) & 1][b_e][h_e] = val;          // consumer-visible write
        }

        // ---- publish (only g_hx must be ordered before it) ----
        __syncthreads();
        if (tid == 0) red_rel_add1(flag);

        // ---- deferred output stores (off the critical path) ----
        if (tid < 512) {
            hidden[oidx] = val;
            if (t == TSTEPS - 1)
                lasth[(size_t)b_e * HDIM + h_e] = val;
        }
    }
}

// ============================================================
// Launch
// ============================================================
extern "C" void kernel_launch(void* const* d_in, const int* in_sizes, int n_in,
                              void* d_out, int out_size) {
    const float* emb = (const float*)d_in[0];   // [B,T,I]
    const float* h0  = (const float*)d_in[1];   // [B,H]
    const float* Wx  = (const float*)d_in[2];   // [H,I]
    const float* bx  = (const float*)d_in[3];   // [H]
    const float* Wh  = (const float*)d_in[4];   // [H,H]
    const float* bh  = (const float*)d_in[5];   // [H]

    float* hidden = (float*)d_out;                            // [B,T,H]
    float* lasth  = hidden + (size_t)BDIM * TSTEPS * HDIM;    // [B,H]

    cudaFuncSetAttribute(rnn_scan, cudaFuncAttributeMaxDynamicSharedMemorySize,
                         SMEM_BYTES);

    // h0 -> exchange buffer, reset flags
    init_h0<<<64, 256>>>(h0);

    // xp = emb @ Wx^T + bx
    dim3 g1(HDIM / 128, (BDIM * TSTEPS) / 128);
    gemm_xproj<<<g1, 256>>>(emb, Wx, bx, hidden);

    // dataflow-synced persistent scan
    rnn_scan<<<NCTAS, NTHREADS, SMEM_BYTES>>>(hidden, Wh, bh, lasth);
}